// round 4
// baseline (speedup 1.0000x reference)
#include <cuda_runtime.h>
#include <cuda_bf16.h>
#include <cstdint>

// ---------------- problem sizes ----------------
#define M_TOT   4096      // B*S
#define N_TOT   8192      // out_features
#define K_IN    2048      // in_features
#define KTOT    6144      // 3 * K_IN (split-precision concat)

// ---------------- GEMM tiling ----------------
#define BM      256
#define BN      128
#define BK      64
#define STAGES  3
#define NSTEPS  (KTOT / BK)         // 96
#define MT2     (M_TOT / BM)        // 16
#define NT2     (N_TOT / BN)        // 64

#define A_BYTES (BM * 128)          // 32768 (BK*2 = 128B per row)
#define B_BYTES (BN * 128)          // 16384
#define STAGE_BYTES (A_BYTES + B_BYTES)          // 49152
#define SMEM_TOTAL  (STAGES * STAGE_BYTES)       // 147456

// ---------------- scratch (static device arrays are allowed) ----------------
__device__ __nv_bfloat16 g_A[(size_t)M_TOT * KTOT];   // 48 MB  [Xh | Xh | Xl]
__device__ __nv_bfloat16 g_B[(size_t)N_TOT * KTOT];   // 96 MB  [Wh | Wl | Wh]

__constant__ float c_lut[15] = {-1.0f,-0.5f,-0.333333f,-0.2f,-0.142857f,-0.090909f,
                                -0.076923f,0.0f,0.076923f,0.090909f,0.142857f,0.2f,
                                0.333333f,0.5f,1.0f};

// ---------------- PTX helpers (baseline sm_80/sm_90 features only) ----------------
__device__ __forceinline__ uint32_t smem_u32(const void* p) {
    uint32_t a;
    asm("{ .reg .u64 t; cvta.to.shared.u64 t, %1; cvt.u32.u64 %0, t; }" : "=r"(a) : "l"(p));
    return a;
}
// 128B-row swizzle: XOR 16B-chunk index (bits 4-6) with row low bits (bits 7-9)
#define SWZ(o) ((o) ^ (((o) >> 3) & 0x70))

__device__ __forceinline__ void cp_async16(uint32_t dst, const void* src) {
    asm volatile("cp.async.cg.shared.global [%0], [%1], 16;" :: "r"(dst), "l"(src) : "memory");
}
__device__ __forceinline__ void cp_commit() {
    asm volatile("cp.async.commit_group;" ::: "memory");
}
template <int N>
__device__ __forceinline__ void cp_wait() {
    asm volatile("cp.async.wait_group %0;" :: "n"(N) : "memory");
}
__device__ __forceinline__ void ldsm4(uint32_t* r, uint32_t addr) {
    asm volatile("ldmatrix.sync.aligned.m8n8.x4.shared.b16 {%0,%1,%2,%3}, [%4];"
        : "=r"(r[0]), "=r"(r[1]), "=r"(r[2]), "=r"(r[3]) : "r"(addr));
}
__device__ __forceinline__ void mma16816(float* d, const uint32_t* a, uint32_t b0, uint32_t b1) {
    asm volatile("mma.sync.aligned.m16n8k16.row.col.f32.bf16.bf16.f32 "
        "{%0,%1,%2,%3}, {%4,%5,%6,%7}, {%8,%9}, {%0,%1,%2,%3};"
        : "+f"(d[0]), "+f"(d[1]), "+f"(d[2]), "+f"(d[3])
        : "r"(a[0]), "r"(a[1]), "r"(a[2]), "r"(a[3]), "r"(b0), "r"(b1));
}

// ---------------- kernel 1: dequant + hi/lo split of W ----------------
struct alignas(8) B4 { __nv_bfloat16 v[4]; };

__global__ void dequant_w_kernel(const int* __restrict__ gi, const float* __restrict__ scale) {
    int t = blockIdx.x * blockDim.x + threadIdx.x;          // 4,194,304 threads
    float s = *scale;
    int4 q = reinterpret_cast<const int4*>(gi)[t];
    long e = (long)t * 4;
    long o = e >> 11;                 // / 2048
    int  i = (int)(e & 2047);
    float f0 = c_lut[q.x] * s, f1 = c_lut[q.y] * s, f2 = c_lut[q.z] * s, f3 = c_lut[q.w] * s;
    __nv_bfloat16 h0 = __float2bfloat16(f0), h1 = __float2bfloat16(f1);
    __nv_bfloat16 h2 = __float2bfloat16(f2), h3 = __float2bfloat16(f3);
    __nv_bfloat16 l0 = __float2bfloat16(f0 - __bfloat162float(h0));
    __nv_bfloat16 l1 = __float2bfloat16(f1 - __bfloat162float(h1));
    __nv_bfloat16 l2 = __float2bfloat16(f2 - __bfloat162float(h2));
    __nv_bfloat16 l3 = __float2bfloat16(f3 - __bfloat162float(h3));
    B4 hi; hi.v[0]=h0; hi.v[1]=h1; hi.v[2]=h2; hi.v[3]=h3;
    B4 lo; lo.v[0]=l0; lo.v[1]=l1; lo.v[2]=l2; lo.v[3]=l3;
    B4* row = reinterpret_cast<B4*>(g_B + o * KTOT);
    row[i >> 2]             = hi;     // Wh
    row[(2048 + i) >> 2]    = lo;     // Wl
    row[(4096 + i) >> 2]    = hi;     // Wh
}

// ---------------- kernel 2: hi/lo split of X ----------------
__global__ void conv_x_kernel(const float* __restrict__ x) {
    int t = blockIdx.x * blockDim.x + threadIdx.x;          // 2,097,152 threads
    float4 f = reinterpret_cast<const float4*>(x)[t];
    long e = (long)t * 4;
    long m = e >> 11;
    int  i = (int)(e & 2047);
    __nv_bfloat16 h0 = __float2bfloat16(f.x), h1 = __float2bfloat16(f.y);
    __nv_bfloat16 h2 = __float2bfloat16(f.z), h3 = __float2bfloat16(f.w);
    __nv_bfloat16 l0 = __float2bfloat16(f.x - __bfloat162float(h0));
    __nv_bfloat16 l1 = __float2bfloat16(f.y - __bfloat162float(h1));
    __nv_bfloat16 l2 = __float2bfloat16(f.z - __bfloat162float(h2));
    __nv_bfloat16 l3 = __float2bfloat16(f.w - __bfloat162float(h3));
    B4 hi; hi.v[0]=h0; hi.v[1]=h1; hi.v[2]=h2; hi.v[3]=h3;
    B4 lo; lo.v[0]=l0; lo.v[1]=l1; lo.v[2]=l2; lo.v[3]=l3;
    B4* row = reinterpret_cast<B4*>(g_A + m * KTOT);
    row[i >> 2]             = hi;     // Xh
    row[(2048 + i) >> 2]    = hi;     // Xh
    row[(4096 + i) >> 2]    = lo;     // Xl
}

// ---------------- kernel 3: mma.sync bf16 GEMM ----------------
__global__ __launch_bounds__(512, 1)
void gemm_kernel(float* __restrict__ C) {
    extern __shared__ char smem[];
    const uint32_t sb = smem_u32(smem);
    const int tid = threadIdx.x;
    const int bid = blockIdx.x;
    const int nt = bid & (NT2 - 1);
    const int mt = bid >> 6;
    const int m0 = mt * BM, n0 = nt * BN;

    const int lane = tid & 31;
    const int w = tid >> 5;
    const int wm = (w & 3) * 64;      // warp M offset (4 warps in M)
    const int wn = (w >> 2) * 32;     // warp N offset (4 warps in N)

    const __nv_bfloat16* Abase = g_A + (size_t)m0 * KTOT;
    const __nv_bfloat16* Bbase = g_B + (size_t)n0 * KTOT;

    // ---- per-lane ldmatrix address components ----
    // A fragment (m16k16, x4): row = wm + mi*16 + (lane&7) + ((lane>>3)&1)*8
    //                          colbyte = kk*32 + (lane>>4)*16
    const int a_row   = wm + (lane & 7) + ((lane >> 3) & 1) * 8;
    const uint32_t a_rowoff = (uint32_t)a_row * 128;
    const uint32_t a_colx   = (uint32_t)((a_row & 7) << 4);
    const uint32_t a_kh     = (uint32_t)((lane >> 4) * 16);
    // B fragment pairs (2 x n8k16 per ldmatrix.x4):
    // row = wn + pair*16 + (lane&7) + ((lane>>4)<<3), colbyte = kk*32 + ((lane>>3)&1)*16
    const int b_row   = wn + (lane & 7) + ((lane >> 4) << 3);
    const uint32_t b_rowoff = (uint32_t)b_row * 128;
    const uint32_t b_colx   = (uint32_t)((b_row & 7) << 4);
    const uint32_t b_kh     = (uint32_t)(((lane >> 3) & 1) * 16);

    float acc[4][4][4];
    #pragma unroll
    for (int i = 0; i < 4; ++i)
        #pragma unroll
        for (int j = 0; j < 4; ++j)
            #pragma unroll
            for (int q = 0; q < 4; ++q) acc[i][j][q] = 0.0f;

    // ---- stage loader: A (2048 chunks of 16B) + B (1024 chunks), 512 threads ----
    auto load_stage = [&](int stage, int k0) {
        uint32_t sA = sb + stage * STAGE_BYTES;
        uint32_t sB = sA + A_BYTES;
        #pragma unroll
        for (int i = 0; i < 4; ++i) {
            int c = tid + i * 512;
            int row = c >> 3, ch = c & 7;
            uint32_t off = (uint32_t)row * 128 + (uint32_t)ch * 16;
            cp_async16(sA + SWZ(off), Abase + (size_t)row * KTOT + k0 + ch * 8);
        }
        #pragma unroll
        for (int i = 0; i < 2; ++i) {
            int c = tid + i * 512;
            int row = c >> 3, ch = c & 7;
            uint32_t off = (uint32_t)row * 128 + (uint32_t)ch * 16;
            cp_async16(sB + SWZ(off), Bbase + (size_t)row * KTOT + k0 + ch * 8);
        }
    };

    // ---- prefetch ----
    #pragma unroll
    for (int s = 0; s < STAGES - 1; ++s) { load_stage(s, s * BK); cp_commit(); }

    // ---- main loop ----
    #pragma unroll 1
    for (int it = 0; it < NSTEPS; ++it) {
        cp_wait<STAGES - 2>();
        __syncthreads();

        int ld = it + STAGES - 1;
        if (ld < NSTEPS) load_stage(ld % STAGES, ld * BK);
        cp_commit();

        const int stage = it % STAGES;
        const uint32_t sA = sb + stage * STAGE_BYTES;
        const uint32_t sB = sA + A_BYTES;

        #pragma unroll
        for (int kk = 0; kk < 4; ++kk) {
            uint32_t a[4][4];
            #pragma unroll
            for (int mi = 0; mi < 4; ++mi) {
                uint32_t addr = sA + a_rowoff + (uint32_t)(mi * 2048)
                              + (((uint32_t)(kk * 32) + a_kh) ^ a_colx);
                ldsm4(a[mi], addr);
            }
            uint32_t b[2][4];
            #pragma unroll
            for (int pi = 0; pi < 2; ++pi) {
                uint32_t addr = sB + b_rowoff + (uint32_t)(pi * 2048)
                              + (((uint32_t)(kk * 32) + b_kh) ^ b_colx);
                ldsm4(b[pi], addr);
            }
            #pragma unroll
            for (int mi = 0; mi < 4; ++mi) {
                #pragma unroll
                for (int ni = 0; ni < 4; ++ni) {
                    mma16816(acc[mi][ni], a[mi], b[ni >> 1][(ni & 1) * 2],
                             b[ni >> 1][(ni & 1) * 2 + 1]);
                }
            }
        }
    }

    // ---- epilogue: registers -> GMEM (fp32) ----
    #pragma unroll
    for (int mi = 0; mi < 4; ++mi) {
        #pragma unroll
        for (int ni = 0; ni < 4; ++ni) {
            int row = m0 + wm + mi * 16 + (lane >> 2);
            int col = n0 + wn + ni * 8 + (lane & 3) * 2;
            float2* p0 = reinterpret_cast<float2*>(C + (size_t)row * N_TOT + col);
            float2* p1 = reinterpret_cast<float2*>(C + (size_t)(row + 8) * N_TOT + col);
            *p0 = make_float2(acc[mi][ni][0], acc[mi][ni][1]);
            *p1 = make_float2(acc[mi][ni][2], acc[mi][ni][3]);
        }
    }
}

// ---------------- launch ----------------
extern "C" void kernel_launch(void* const* d_in, const int* in_sizes, int n_in,
                              void* d_out, int out_size) {
    const float* x     = (const float*)d_in[0];
    const int*   gi    = (const int*)d_in[1];
    const float* scale = (const float*)d_in[2];
    float*       out   = (float*)d_out;

    cudaFuncSetAttribute(gemm_kernel, cudaFuncAttributeMaxDynamicSharedMemorySize, SMEM_TOTAL);

    dequant_w_kernel<<<(N_TOT * K_IN / 4) / 256, 256>>>(gi, scale);
    conv_x_kernel<<<(M_TOT * K_IN / 4) / 256, 256>>>(x);
    gemm_kernel<<<MT2 * NT2, 512, SMEM_TOTAL>>>(out);
}

// round 6
// speedup vs baseline: 2.5341x; 2.5341x over previous
#include <cuda_runtime.h>
#include <cuda_fp16.h>
#include <cstdint>

// ---------------- problem sizes ----------------
#define M_TOT   4096      // B*S
#define N_TOT   8192      // out_features
#define K_IN    2048      // in_features

// ---------------- GEMM tiling ----------------
#define BM      128
#define BN      256
#define BK      64
#define STAGES  3
#define NSTEPS  (K_IN / BK)         // 32
#define MT2     (M_TOT / BM)        // 32
#define NT2     (N_TOT / BN)        // 32

#define A_BYTES (BM * 128)          // 16384 (BK*2 = 128B per row)
#define B_BYTES (BN * 128)          // 32768
#define STAGE_BYTES (A_BYTES + B_BYTES)          // 49152
#define SMEM_TOTAL  (STAGES * STAGE_BYTES)       // 147456

// ---------------- scratch (static device arrays are allowed) ----------------
__device__ __half g_A[(size_t)M_TOT * K_IN];   // 16 MB  x in fp16
__device__ __half g_B[(size_t)N_TOT * K_IN];   // 32 MB  w in fp16

__constant__ float c_lut[15] = {-1.0f,-0.5f,-0.333333f,-0.2f,-0.142857f,-0.090909f,
                                -0.076923f,0.0f,0.076923f,0.090909f,0.142857f,0.2f,
                                0.333333f,0.5f,1.0f};

// ---------------- PTX helpers (baseline sm_80 features only) ----------------
__device__ __forceinline__ uint32_t smem_u32(const void* p) {
    uint32_t a;
    asm("{ .reg .u64 t; cvta.to.shared.u64 t, %1; cvt.u32.u64 %0, t; }" : "=r"(a) : "l"(p));
    return a;
}
// 128B-row swizzle: XOR 16B-chunk index (bits 4-6) with row low bits (bits 7-9)
#define SWZ(o) ((o) ^ (((o) >> 3) & 0x70))

__device__ __forceinline__ void cp_async16(uint32_t dst, const void* src) {
    asm volatile("cp.async.cg.shared.global [%0], [%1], 16;" :: "r"(dst), "l"(src) : "memory");
}
__device__ __forceinline__ void cp_commit() {
    asm volatile("cp.async.commit_group;" ::: "memory");
}
template <int N>
__device__ __forceinline__ void cp_wait() {
    asm volatile("cp.async.wait_group %0;" :: "n"(N) : "memory");
}
__device__ __forceinline__ void ldsm4(uint32_t* r, uint32_t addr) {
    asm volatile("ldmatrix.sync.aligned.m8n8.x4.shared.b16 {%0,%1,%2,%3}, [%4];"
        : "=r"(r[0]), "=r"(r[1]), "=r"(r[2]), "=r"(r[3]) : "r"(addr));
}
__device__ __forceinline__ void mma16816(float* d, const uint32_t* a, uint32_t b0, uint32_t b1) {
    asm volatile("mma.sync.aligned.m16n8k16.row.col.f32.f16.f16.f32 "
        "{%0,%1,%2,%3}, {%4,%5,%6,%7}, {%8,%9}, {%0,%1,%2,%3};"
        : "+f"(d[0]), "+f"(d[1]), "+f"(d[2]), "+f"(d[3])
        : "r"(a[0]), "r"(a[1]), "r"(a[2]), "r"(a[3]), "r"(b0), "r"(b1));
}

// ---------------- kernel 1: dequant W -> fp16 ----------------
struct alignas(8) H4 { __half v[4]; };

__global__ void dequant_w_kernel(const int* __restrict__ gi, const float* __restrict__ scale) {
    int t = blockIdx.x * blockDim.x + threadIdx.x;          // 4,194,304 threads
    float s = *scale;
    int4 q = reinterpret_cast<const int4*>(gi)[t];
    H4 h;
    h.v[0] = __float2half(c_lut[q.x] * s);
    h.v[1] = __float2half(c_lut[q.y] * s);
    h.v[2] = __float2half(c_lut[q.z] * s);
    h.v[3] = __float2half(c_lut[q.w] * s);
    reinterpret_cast<H4*>(g_B)[t] = h;
}

// ---------------- kernel 2: X -> fp16 ----------------
__global__ void conv_x_kernel(const float* __restrict__ x) {
    int t = blockIdx.x * blockDim.x + threadIdx.x;          // 2,097,152 threads
    float4 f = reinterpret_cast<const float4*>(x)[t];
    H4 h;
    h.v[0] = __float2half(f.x);
    h.v[1] = __float2half(f.y);
    h.v[2] = __float2half(f.z);
    h.v[3] = __float2half(f.w);
    reinterpret_cast<H4*>(g_A)[t] = h;
}

// ---------------- kernel 3: mma.sync fp16 GEMM ----------------
// 256 threads (8 warps), warp grid 2M x 4N, warp tile 64x64
__global__ __launch_bounds__(256, 1)
void gemm_kernel(float* __restrict__ C) {
    extern __shared__ char smem[];
    const uint32_t sb = smem_u32(smem);
    const int tid = threadIdx.x;
    const int bid = blockIdx.x;
    const int nt = bid & (NT2 - 1);
    const int mt = bid >> 5;
    const int m0 = mt * BM, n0 = nt * BN;

    const int lane = tid & 31;
    const int w = tid >> 5;
    const int wm = (w & 1) * 64;      // warp M offset (2 warps in M)
    const int wn = (w >> 1) * 64;     // warp N offset (4 warps in N)

    const __half* Abase = g_A + (size_t)m0 * K_IN;
    const __half* Bbase = g_B + (size_t)n0 * K_IN;

    // ---- per-lane ldmatrix address components ----
    // A fragment (m16k16, x4): row = wm + mi*16 + (lane&7) + ((lane>>3)&1)*8
    //                          colbyte = kk*32 + (lane>>4)*16
    const int a_row   = wm + (lane & 7) + ((lane >> 3) & 1) * 8;
    const uint32_t a_rowoff = (uint32_t)a_row * 128;
    const uint32_t a_colx   = (uint32_t)((a_row & 7) << 4);
    const uint32_t a_kh     = (uint32_t)((lane >> 4) * 16);
    // B fragment pairs (2 x n8k16 per ldmatrix.x4):
    // row = wn + pair*16 + (lane&7) + ((lane>>4)<<3), colbyte = kk*32 + ((lane>>3)&1)*16
    const int b_row   = wn + (lane & 7) + ((lane >> 4) << 3);
    const uint32_t b_rowoff = (uint32_t)b_row * 128;
    const uint32_t b_colx   = (uint32_t)((b_row & 7) << 4);
    const uint32_t b_kh     = (uint32_t)(((lane >> 3) & 1) * 16);

    float acc[4][8][4];
    #pragma unroll
    for (int i = 0; i < 4; ++i)
        #pragma unroll
        for (int j = 0; j < 8; ++j)
            #pragma unroll
            for (int q = 0; q < 4; ++q) acc[i][j][q] = 0.0f;

    // ---- stage loader: A (1024 chunks of 16B) + B (2048 chunks), 256 threads ----
    auto load_stage = [&](int stage, int k0) {
        uint32_t sA = sb + stage * STAGE_BYTES;
        uint32_t sB = sA + A_BYTES;
        #pragma unroll
        for (int i = 0; i < 4; ++i) {
            int c = tid + i * 256;
            int row = c >> 3, ch = c & 7;
            uint32_t off = (uint32_t)row * 128 + (uint32_t)ch * 16;
            cp_async16(sA + SWZ(off), Abase + (size_t)row * K_IN + k0 + ch * 8);
        }
        #pragma unroll
        for (int i = 0; i < 8; ++i) {
            int c = tid + i * 256;
            int row = c >> 3, ch = c & 7;
            uint32_t off = (uint32_t)row * 128 + (uint32_t)ch * 16;
            cp_async16(sB + SWZ(off), Bbase + (size_t)row * K_IN + k0 + ch * 8);
        }
    };

    // ---- prefetch ----
    #pragma unroll
    for (int s = 0; s < STAGES - 1; ++s) { load_stage(s, s * BK); cp_commit(); }

    // ---- main loop ----
    #pragma unroll 1
    for (int it = 0; it < NSTEPS; ++it) {
        cp_wait<STAGES - 2>();
        __syncthreads();

        int ld = it + STAGES - 1;
        if (ld < NSTEPS) load_stage(ld % STAGES, ld * BK);
        cp_commit();

        const int stage = it % STAGES;
        const uint32_t sA = sb + stage * STAGE_BYTES;
        const uint32_t sB = sA + A_BYTES;

        #pragma unroll
        for (int kk = 0; kk < 4; ++kk) {
            uint32_t a[4][4];
            #pragma unroll
            for (int mi = 0; mi < 4; ++mi) {
                uint32_t addr = sA + a_rowoff + (uint32_t)(mi * 2048)
                              + (((uint32_t)(kk * 32) + a_kh) ^ a_colx);
                ldsm4(a[mi], addr);
            }
            uint32_t b[4][4];
            #pragma unroll
            for (int pi = 0; pi < 4; ++pi) {
                uint32_t addr = sB + b_rowoff + (uint32_t)(pi * 2048)
                              + (((uint32_t)(kk * 32) + b_kh) ^ b_colx);
                ldsm4(b[pi], addr);
            }
            #pragma unroll
            for (int mi = 0; mi < 4; ++mi) {
                #pragma unroll
                for (int ni = 0; ni < 8; ++ni) {
                    mma16816(acc[mi][ni], a[mi], b[ni >> 1][(ni & 1) * 2],
                             b[ni >> 1][(ni & 1) * 2 + 1]);
                }
            }
        }
    }

    // ---- epilogue: registers -> GMEM (fp32) ----
    #pragma unroll
    for (int mi = 0; mi < 4; ++mi) {
        #pragma unroll
        for (int ni = 0; ni < 8; ++ni) {
            int row = m0 + wm + mi * 16 + (lane >> 2);
            int col = n0 + wn + ni * 8 + (lane & 3) * 2;
            float2* p0 = reinterpret_cast<float2*>(C + (size_t)row * N_TOT + col);
            float2* p1 = reinterpret_cast<float2*>(C + (size_t)(row + 8) * N_TOT + col);
            *p0 = make_float2(acc[mi][ni][0], acc[mi][ni][1]);
            *p1 = make_float2(acc[mi][ni][2], acc[mi][ni][3]);
        }
    }
}

// ---------------- launch ----------------
extern "C" void kernel_launch(void* const* d_in, const int* in_sizes, int n_in,
                              void* d_out, int out_size) {
    const float* x     = (const float*)d_in[0];
    const int*   gi    = (const int*)d_in[1];
    const float* scale = (const float*)d_in[2];
    float*       out   = (float*)d_out;

    cudaFuncSetAttribute(gemm_kernel, cudaFuncAttributeMaxDynamicSharedMemorySize, SMEM_TOTAL);

    dequant_w_kernel<<<(N_TOT * K_IN / 4) / 256, 256>>>(gi, scale);
    conv_x_kernel<<<(M_TOT * K_IN / 4) / 256, 256>>>(x);
    gemm_kernel<<<MT2 * NT2, 256, SMEM_TOTAL>>>(out);
}

// round 8
// speedup vs baseline: 2.7915x; 1.1016x over previous
#include <cuda_runtime.h>
#include <cuda_fp16.h>
#include <cstdint>

// ---------------- problem sizes ----------------
#define M_TOT   4096      // B*S
#define N_TOT   8192      // out_features
#define K_IN    2048      // in_features

// ---------------- GEMM tiling ----------------
#define BM      256
#define BN      128
#define BK      64
#define STAGES  4
#define NSTEPS  (K_IN / BK)         // 32
#define MT2     (M_TOT / BM)        // 16
#define NT2     (N_TOT / BN)        // 64

#define A_BYTES (BM * 128)          // 32768 (BK*2 = 128B per row)
#define B_BYTES (BN * 128)          // 16384
#define STAGE_BYTES (A_BYTES + B_BYTES)          // 49152
#define SMEM_TOTAL  (STAGES * STAGE_BYTES)       // 196608

// prep kernel split
#define W_BLOCKS  ((N_TOT * K_IN / 4) / 256)     // 16384
#define X_BLOCKS  ((M_TOT * K_IN / 4) / 256)     // 8192

// ---------------- scratch (static device arrays are allowed) ----------------
__device__ __half g_A[(size_t)M_TOT * K_IN];   // 16 MB  x in fp16
__device__ __half g_B[(size_t)N_TOT * K_IN];   // 32 MB  w in fp16

__constant__ float c_lut[16] = {-1.0f,-0.5f,-0.333333f,-0.2f,-0.142857f,-0.090909f,
                                -0.076923f,0.0f,0.076923f,0.090909f,0.142857f,0.2f,
                                0.333333f,0.5f,1.0f,0.0f};

// ---------------- PTX helpers (baseline sm_80 features only) ----------------
__device__ __forceinline__ uint32_t smem_u32(const void* p) {
    uint32_t a;
    asm("{ .reg .u64 t; cvta.to.shared.u64 t, %1; cvt.u32.u64 %0, t; }" : "=r"(a) : "l"(p));
    return a;
}
// 128B-row swizzle: XOR 16B-chunk index (bits 4-6) with row low bits (bits 7-9)
#define SWZ(o) ((o) ^ (((o) >> 3) & 0x70))

__device__ __forceinline__ void cp_async16(uint32_t dst, const void* src) {
    asm volatile("cp.async.cg.shared.global [%0], [%1], 16;" :: "r"(dst), "l"(src) : "memory");
}
__device__ __forceinline__ void cp_commit() {
    asm volatile("cp.async.commit_group;" ::: "memory");
}
template <int N>
__device__ __forceinline__ void cp_wait() {
    asm volatile("cp.async.wait_group %0;" :: "n"(N) : "memory");
}
__device__ __forceinline__ void ldsm4(uint32_t* r, uint32_t addr) {
    asm volatile("ldmatrix.sync.aligned.m8n8.x4.shared.b16 {%0,%1,%2,%3}, [%4];"
        : "=r"(r[0]), "=r"(r[1]), "=r"(r[2]), "=r"(r[3]) : "r"(addr));
}
__device__ __forceinline__ void mma16816(float* d, const uint32_t* a, uint32_t b0, uint32_t b1) {
    asm volatile("mma.sync.aligned.m16n8k16.row.col.f32.f16.f16.f32 "
        "{%0,%1,%2,%3}, {%4,%5,%6,%7}, {%8,%9}, {%0,%1,%2,%3};"
        : "+f"(d[0]), "+f"(d[1]), "+f"(d[2]), "+f"(d[3])
        : "r"(a[0]), "r"(a[1]), "r"(a[2]), "r"(a[3]), "r"(b0), "r"(b1));
}

// ---------------- kernel 1: fused prep (dequant W + convert X) ----------------
struct alignas(8) H4 { __half v[4]; };

__global__ void prep_kernel(const float* __restrict__ x, const int* __restrict__ gi,
                            const float* __restrict__ scale) {
    const int lane = threadIdx.x & 31;
    const int b = blockIdx.x;
    if (b < W_BLOCKS) {
        // LUT lives in one register per lane; lookups via shfl (no const-cache replay)
        const float lv = c_lut[lane & 15];
        const float s = *scale;
        int t = b * 256 + threadIdx.x;
        int4 q = reinterpret_cast<const int4*>(gi)[t];
        float f0 = __shfl_sync(0xffffffffu, lv, q.x) * s;
        float f1 = __shfl_sync(0xffffffffu, lv, q.y) * s;
        float f2 = __shfl_sync(0xffffffffu, lv, q.z) * s;
        float f3 = __shfl_sync(0xffffffffu, lv, q.w) * s;
        H4 h;
        h.v[0] = __float2half(f0);
        h.v[1] = __float2half(f1);
        h.v[2] = __float2half(f2);
        h.v[3] = __float2half(f3);
        reinterpret_cast<H4*>(g_B)[t] = h;
    } else {
        int t = (b - W_BLOCKS) * 256 + threadIdx.x;
        float4 f = reinterpret_cast<const float4*>(x)[t];
        H4 h;
        h.v[0] = __float2half(f.x);
        h.v[1] = __float2half(f.y);
        h.v[2] = __float2half(f.z);
        h.v[3] = __float2half(f.w);
        reinterpret_cast<H4*>(g_A)[t] = h;
    }
}

// ---------------- kernel 2: mma.sync fp16 GEMM ----------------
// 512 threads (16 warps), warp grid 4M x 4N, warp tile 64x32
__global__ __launch_bounds__(512, 1)
void gemm_kernel(float* __restrict__ C) {
    extern __shared__ char smem[];
    const uint32_t sb = smem_u32(smem);
    const int tid = threadIdx.x;
    const int bid = blockIdx.x;
    const int nt = bid & (NT2 - 1);
    const int mt = bid >> 6;
    const int m0 = mt * BM, n0 = nt * BN;

    const int lane = tid & 31;
    const int w = tid >> 5;
    const int wm = (w & 3) * 64;      // warp M offset (4 warps in M)
    const int wn = (w >> 2) * 32;     // warp N offset (4 warps in N)

    const __half* Abase = g_A + (size_t)m0 * K_IN;
    const __half* Bbase = g_B + (size_t)n0 * K_IN;

    // ---- per-lane ldmatrix address components ----
    const int a_row   = wm + (lane & 7) + ((lane >> 3) & 1) * 8;
    const uint32_t a_rowoff = (uint32_t)a_row * 128;
    const uint32_t a_colx   = (uint32_t)((a_row & 7) << 4);
    const uint32_t a_kh     = (uint32_t)((lane >> 4) * 16);
    const int b_row   = wn + (lane & 7) + ((lane >> 4) << 3);
    const uint32_t b_rowoff = (uint32_t)b_row * 128;
    const uint32_t b_colx   = (uint32_t)((b_row & 7) << 4);
    const uint32_t b_kh     = (uint32_t)(((lane >> 3) & 1) * 16);

    float acc[4][4][4];
    #pragma unroll
    for (int i = 0; i < 4; ++i)
        #pragma unroll
        for (int j = 0; j < 4; ++j)
            #pragma unroll
            for (int q = 0; q < 4; ++q) acc[i][j][q] = 0.0f;

    // ---- stage loader: A (2048 chunks of 16B) + B (1024 chunks), 512 threads ----
    auto load_stage = [&](int stage, int k0) {
        uint32_t sA = sb + stage * STAGE_BYTES;
        uint32_t sB = sA + A_BYTES;
        #pragma unroll
        for (int i = 0; i < 4; ++i) {
            int c = tid + i * 512;
            int row = c >> 3, ch = c & 7;
            uint32_t off = (uint32_t)row * 128 + (uint32_t)ch * 16;
            cp_async16(sA + SWZ(off), Abase + (size_t)row * K_IN + k0 + ch * 8);
        }
        #pragma unroll
        for (int i = 0; i < 2; ++i) {
            int c = tid + i * 512;
            int row = c >> 3, ch = c & 7;
            uint32_t off = (uint32_t)row * 128 + (uint32_t)ch * 16;
            cp_async16(sB + SWZ(off), Bbase + (size_t)row * K_IN + k0 + ch * 8);
        }
    };

    // ---- prefetch ----
    #pragma unroll
    for (int s = 0; s < STAGES - 1; ++s) { load_stage(s, s * BK); cp_commit(); }

    // ---- main loop ----
    #pragma unroll 1
    for (int it = 0; it < NSTEPS; ++it) {
        cp_wait<STAGES - 2>();
        __syncthreads();

        int ld = it + STAGES - 1;
        if (ld < NSTEPS) load_stage(ld % STAGES, ld * BK);
        cp_commit();

        const int stage = it % STAGES;
        const uint32_t sA = sb + stage * STAGE_BYTES;
        const uint32_t sB = sA + A_BYTES;

        #pragma unroll
        for (int kk = 0; kk < 4; ++kk) {
            uint32_t a[4][4];
            #pragma unroll
            for (int mi = 0; mi < 4; ++mi) {
                uint32_t addr = sA + a_rowoff + (uint32_t)(mi * 2048)
                              + (((uint32_t)(kk * 32) + a_kh) ^ a_colx);
                ldsm4(a[mi], addr);
            }
            uint32_t b[2][4];
            #pragma unroll
            for (int pi = 0; pi < 2; ++pi) {
                uint32_t addr = sB + b_rowoff + (uint32_t)(pi * 2048)
                              + (((uint32_t)(kk * 32) + b_kh) ^ b_colx);
                ldsm4(b[pi], addr);
            }
            #pragma unroll
            for (int mi = 0; mi < 4; ++mi) {
                #pragma unroll
                for (int ni = 0; ni < 4; ++ni) {
                    mma16816(acc[mi][ni], a[mi], b[ni >> 1][(ni & 1) * 2],
                             b[ni >> 1][(ni & 1) * 2 + 1]);
                }
            }
        }
    }

    // ---- epilogue: registers -> GMEM (fp32) ----
    #pragma unroll
    for (int mi = 0; mi < 4; ++mi) {
        #pragma unroll
        for (int ni = 0; ni < 4; ++ni) {
            int row = m0 + wm + mi * 16 + (lane >> 2);
            int col = n0 + wn + ni * 8 + (lane & 3) * 2;
            float2* p0 = reinterpret_cast<float2*>(C + (size_t)row * N_TOT + col);
            float2* p1 = reinterpret_cast<float2*>(C + (size_t)(row + 8) * N_TOT + col);
            *p0 = make_float2(acc[mi][ni][0], acc[mi][ni][1]);
            *p1 = make_float2(acc[mi][ni][2], acc[mi][ni][3]);
        }
    }
}

// ---------------- launch ----------------
extern "C" void kernel_launch(void* const* d_in, const int* in_sizes, int n_in,
                              void* d_out, int out_size) {
    const float* x     = (const float*)d_in[0];
    const int*   gi    = (const int*)d_in[1];
    const float* scale = (const float*)d_in[2];
    float*       out   = (float*)d_out;

    cudaFuncSetAttribute(gemm_kernel, cudaFuncAttributeMaxDynamicSharedMemorySize, SMEM_TOTAL);

    prep_kernel<<<W_BLOCKS + X_BLOCKS, 256>>>(x, gi, scale);
    gemm_kernel<<<MT2 * NT2, 512, SMEM_TOTAL>>>(out);
}